// round 13
// baseline (speedup 1.0000x reference)
#include <cuda_runtime.h>

#define MAXN 50000
#define MAXB 16

typedef unsigned long long ull;

// packed f32x2 helpers (Blackwell double-rate fp32 path — ptxas never auto-emits)
#define PK2(out, lo, hi) asm("mov.b64 %0, {%1, %2};" : "=l"(out) : "f"(lo), "f"(hi))
#define UPK2(lo, hi, in) asm("mov.b64 {%0, %1}, %2;" : "=f"(lo), "=f"(hi) : "l"(in))
#define FMA2(d, a, b, c) asm("fma.rn.f32x2 %0, %1, %2, %3;" : "=l"(d) : "l"(a), "l"(b), "l"(c))

union F4U { float4 f; ull u[2]; };

// ---------------- device-global scratch (no allocations allowed) ----------------
__device__ float g_xa[MAXN * 32];
__device__ float g_xb[MAXN * 32];
__device__ float g_s[MAXN * 64];    // x[n] @ W1_edge[0:32,:]   (src block)
__device__ float g_d[MAXN * 64];    // x[n] @ W1_edge[32:64,:]  (dst block)
__device__ float g_agg[MAXN * 32];  // scatter-sum of e -> dst
__device__ float g_u[MAXB * 32];
__device__ float g_bsum[MAXB * 32]; // scatter-sum of x -> batch
__device__ float g_deg[MAXN];
__device__ float g_gcnt[MAXB];
__device__ float g_uWe[MAXB * 64];  // u @ W1_edge[96:128,:] + b1_edge
__device__ float g_uWn[MAXB * 64];  // u @ W1_node[64:96,:]  + b1_node

// ---------------- small utility kernels ----------------
__global__ void zero_k(float* p, int n) {
    int i = blockIdx.x * blockDim.x + threadIdx.x;
    if (i < n) p[i] = 0.f;
}

__global__ void bn_k(const float* __restrict__ x, const float* __restrict__ gamma,
                     const float* __restrict__ beta, float* __restrict__ y, int total) {
    int i = blockIdx.x * blockDim.x + threadIdx.x;
    if (i < total) {
        int c = i & 31;
        y[i] = x[i] * (gamma[c] * rsqrtf(1.f + 1e-5f)) + beta[c];
    }
}

__global__ void deg_k(const int* __restrict__ dst, int E) {
    int e = blockIdx.x * blockDim.x + threadIdx.x;
    if (e < E) atomicAdd(&g_deg[dst[e]], 1.f);
}

__global__ void gcnt_k(const int* __restrict__ batch, int N) {
    __shared__ float sc[MAXB];
    int tid = threadIdx.x;
    if (tid < MAXB) sc[tid] = 0.f;
    __syncthreads();
    int i = blockIdx.x * blockDim.x + tid;
    if (i < N) atomicAdd(&sc[batch[i]], 1.f);
    __syncthreads();
    if (tid < MAXB) atomicAdd(&g_gcnt[tid], sc[tid]);
}

// per-batch u contributions to the edge/node layer-1 activations (+bias)
__global__ void uw_k(const float* __restrict__ eW1u, const float* __restrict__ eb1,
                     const float* __restrict__ nW1u, const float* __restrict__ nb1) {
    int b = blockIdx.x;
    int t = threadIdx.x;
    int j = t & 63;
    const float* uu = g_u + b * 32;
    if (t < 64) {
        float acc = eb1[j];
#pragma unroll
        for (int k = 0; k < 32; k++) acc += uu[k] * eW1u[k * 64 + j];
        g_uWe[b * 64 + j] = acc;
    } else {
        float acc = nb1[j];
#pragma unroll
        for (int k = 0; k < 32; k++) acc += uu[k] * nW1u[k * 64 + j];
        g_uWn[b * 64 + j] = acc;
    }
}

// fused: glob BN -> g_u, then uWe/uWn precompute (layer 0)
__global__ void bnglob_uw_k(const float* __restrict__ glob_feats,
                            const float* __restrict__ gg, const float* __restrict__ gb,
                            const float* __restrict__ eW1u, const float* __restrict__ eb1,
                            const float* __restrict__ nW1u, const float* __restrict__ nb1) {
    int b = blockIdx.x;
    int t = threadIdx.x;  // 128
    __shared__ float su[32];
    if (t < 32) {
        float v = glob_feats[b * 32 + t] * (gg[t] * rsqrtf(1.f + 1e-5f)) + gb[t];
        g_u[b * 32 + t] = v;
        su[t] = v;
    }
    __syncthreads();
    int j = t & 63;
    if (t < 64) {
        float acc = eb1[j];
#pragma unroll
        for (int k = 0; k < 32; k++) acc += su[k] * eW1u[k * 64 + j];
        g_uWe[b * 64 + j] = acc;
    } else {
        float acc = nb1[j];
#pragma unroll
        for (int k = 0; k < 32; k++) acc += su[k] * nW1u[k * 64 + j];
        g_uWn[b * 64 + j] = acc;
    }
}

// per-node precompute: s[n] = x[n] @ W1e[0:32,:], d[n] = x[n] @ W1e[32:64,:]
// also zeroes g_agg row n (fused)
__global__ void __launch_bounds__(256) sd_k(const float* __restrict__ x,
                                            const float* __restrict__ W1sd, int N,
                                            int zeroAgg) {
    __shared__ float sW[64 * 64];
    int tid = threadIdx.x;
    for (int i = tid; i < 4096; i += 256) sW[i] = W1sd[i];
    __syncthreads();
    int n = blockIdx.x * 256 + tid;
    if (n >= N) return;

    if (zeroAgg) {
        float4 z = make_float4(0.f, 0.f, 0.f, 0.f);
        float4* az = (float4*)(g_agg + (size_t)n * 32);
#pragma unroll
        for (int q = 0; q < 8; q++) az[q] = z;
    }

    float xv[32];
    const float4* xp = (const float4*)(x + (size_t)n * 32);
#pragma unroll
    for (int k = 0; k < 8; k++) {
        float4 v = xp[k];
        xv[4 * k] = v.x; xv[4 * k + 1] = v.y; xv[4 * k + 2] = v.z; xv[4 * k + 3] = v.w;
    }

    ull acc[32];
#pragma unroll
    for (int j = 0; j < 32; j++) acc[j] = 0ull;
#pragma unroll 4
    for (int k = 0; k < 32; k++) {
        ull xkp; PK2(xkp, xv[k], xv[k]);
#pragma unroll
        for (int j4 = 0; j4 < 16; j4++) {
            F4U w; w.f = *(const float4*)&sW[k * 64 + j4 * 4];
            FMA2(acc[2 * j4], xkp, w.u[0], acc[2 * j4]);
            FMA2(acc[2 * j4 + 1], xkp, w.u[1], acc[2 * j4 + 1]);
        }
    }
    float4* sp = (float4*)(g_s + (size_t)n * 64);
#pragma unroll
    for (int j4 = 0; j4 < 16; j4++) {
        F4U o; o.u[0] = acc[2 * j4]; o.u[1] = acc[2 * j4 + 1];
        sp[j4] = o.f;
    }

#pragma unroll
    for (int j = 0; j < 32; j++) acc[j] = 0ull;
#pragma unroll 4
    for (int k = 0; k < 32; k++) {
        ull xkp; PK2(xkp, xv[k], xv[k]);
#pragma unroll
        for (int j4 = 0; j4 < 16; j4++) {
            F4U w; w.f = *(const float4*)&sW[(32 + k) * 64 + j4 * 4];
            FMA2(acc[2 * j4], xkp, w.u[0], acc[2 * j4]);
            FMA2(acc[2 * j4 + 1], xkp, w.u[1], acc[2 * j4 + 1]);
        }
    }
    float4* dp = (float4*)(g_d + (size_t)n * 64);
#pragma unroll
    for (int j4 = 0; j4 < 16; j4++) {
        F4U o; o.u[0] = acc[2 * j4]; o.u[1] = acc[2 * j4 + 1];
        dp[j4] = o.f;
    }
}

// ---------------- tiled edge kernel: 128 edges per 256-thread block ----------------
// Interleaved row maps (rows 1 apart within a warp) + float4 broadcast loads of
// the activation operand: 1 LDS.128 per row per 4 k-steps, conflict-free.
#define TE 128
#define EIN_P 36
#define H_P 68

struct ESm {
    float sWe[32 * 64];      // W1 e-block (rows 64..96), [k][c]
    float sW2[64 * 32];      // [k][c]
    float sU[MAXB * 64];
    float sb2[32];
    float sEin[TE * EIN_P];  // edge feats [row][k], pitch 36 (float4-aligned)
    float sH[TE * H_P];      // hidden [row][k], pitch 68 (float4-aligned)
    int sSrc[TE];
    int sDst[TE];
    int sBs[TE];
};

__global__ void __launch_bounds__(256, 2) edge2_k(
    const int* __restrict__ src, const int* __restrict__ dstA,
    const int* __restrict__ batch,
    const float* __restrict__ W1e, const float* __restrict__ W2,
    const float* __restrict__ b2,
    const float* __restrict__ ein,          // raw edge feats (l0) or current e
    const float* __restrict__ bn_gamma,     // non-null => apply BN to ein
    const float* __restrict__ bn_beta,
    float* __restrict__ eout, int E) {
    extern __shared__ char smem_raw[];
    ESm& sm = *(ESm*)smem_raw;

    int tid = threadIdx.x;
    int eBase = blockIdx.x * TE;

    // ---- stage weights / tables ----
    for (int i = tid; i < 2048; i += 256) { sm.sWe[i] = W1e[i]; sm.sW2[i] = W2[i]; }
    for (int i = tid; i < MAXB * 64; i += 256) sm.sU[i] = g_uWe[i];
    if (tid < 32) sm.sb2[tid] = b2[tid];

    // ---- stage indices ----
    if (tid < TE) {
        int e = eBase + tid;
        int s = 0, d = 0, bs = 0;
        if (e < E) { s = src[e]; d = dstA[e]; bs = batch[s]; }
        sm.sSrc[tid] = s; sm.sDst[tid] = d; sm.sBs[tid] = bs;
    }

    // ---- stage edge features (optionally with BN), 2 threads per edge ----
    {
        int el = tid >> 1;
        int e = eBase + el;
        int off = (tid & 1) * 16;
        if (e < E) {
            const float4* p = (const float4*)(ein + (size_t)e * 32 + off);
#pragma unroll
            for (int q = 0; q < 4; q++) {
                float4 v = p[q];
                if (bn_gamma) {
                    int c = off + 4 * q;
                    float r = rsqrtf(1.f + 1e-5f);
                    v.x = v.x * (__ldg(bn_gamma + c)     * r) + __ldg(bn_beta + c);
                    v.y = v.y * (__ldg(bn_gamma + c + 1) * r) + __ldg(bn_beta + c + 1);
                    v.z = v.z * (__ldg(bn_gamma + c + 2) * r) + __ldg(bn_beta + c + 2);
                    v.w = v.w * (__ldg(bn_gamma + c + 3) * r) + __ldg(bn_beta + c + 3);
                }
                *(float4*)&sm.sEin[el * EIN_P + off + 4 * q] = v;
            }
        }
    }
    __syncthreads();

    // ---- GEMM1: H[128x64] = relu(s[src]+d[dst]+uWe[bs] + Ein[128x32] @ We[32x64]) ----
    // rows = ty + 16*i (warp halves handle adjacent rows -> conflict-free broadcasts)
    {
        int tx = tid & 15, ty = tid >> 4;
        int c0 = tx * 4;
        ull acc0[8], acc1[8];
#pragma unroll
        for (int i = 0; i < 8; i++) {
            int row = ty + 16 * i;
            int s = sm.sSrc[row], d = sm.sDst[row], bs = sm.sBs[row];
            float4 a = *(const float4*)(g_s + (size_t)s * 64 + c0);
            float4 b = *(const float4*)(g_d + (size_t)d * 64 + c0);
            const float* up = sm.sU + bs * 64 + c0;
            PK2(acc0[i], a.x + b.x + up[0], a.y + b.y + up[1]);
            PK2(acc1[i], a.z + b.z + up[2], a.w + b.w + up[3]);
        }
#pragma unroll
        for (int kk = 0; kk < 8; kk++) {
            F4U w0, w1, w2, w3;
            w0.f = *(float4*)&sm.sWe[(4 * kk + 0) * 64 + c0];
            w1.f = *(float4*)&sm.sWe[(4 * kk + 1) * 64 + c0];
            w2.f = *(float4*)&sm.sWe[(4 * kk + 2) * 64 + c0];
            w3.f = *(float4*)&sm.sWe[(4 * kk + 3) * 64 + c0];
#pragma unroll
            for (int i = 0; i < 8; i++) {
                int row = ty + 16 * i;
                float4 e4 = *(const float4*)&sm.sEin[row * EIN_P + 4 * kk];
                ull p;
                PK2(p, e4.x, e4.x);
                FMA2(acc0[i], p, w0.u[0], acc0[i]); FMA2(acc1[i], p, w0.u[1], acc1[i]);
                PK2(p, e4.y, e4.y);
                FMA2(acc0[i], p, w1.u[0], acc0[i]); FMA2(acc1[i], p, w1.u[1], acc1[i]);
                PK2(p, e4.z, e4.z);
                FMA2(acc0[i], p, w2.u[0], acc0[i]); FMA2(acc1[i], p, w2.u[1], acc1[i]);
                PK2(p, e4.w, e4.w);
                FMA2(acc0[i], p, w3.u[0], acc0[i]); FMA2(acc1[i], p, w3.u[1], acc1[i]);
            }
        }
#pragma unroll
        for (int i = 0; i < 8; i++) {
            int row = ty + 16 * i;
            float4 r;
            UPK2(r.x, r.y, acc0[i]);
            UPK2(r.z, r.w, acc1[i]);
            r.x = fmaxf(r.x, 0.f); r.y = fmaxf(r.y, 0.f);
            r.z = fmaxf(r.z, 0.f); r.w = fmaxf(r.w, 0.f);
            *(float4*)&sm.sH[row * H_P + c0] = r;
        }
    }
    __syncthreads();

    // ---- GEMM2: O[128x32] = H @ W2[64x32] + b2; write e; scatter-add to agg ----
    // rows = ty2 + 32*i (4 consecutive ty2 per warp -> conflict-free broadcasts)
    {
        int tx2 = tid & 7, ty2 = tid >> 3;
        int c2 = tx2 * 4;
        ull o0[4], o1[4];
        {
            float4 bb = *(float4*)&sm.sb2[c2];
            ull b0, b1; PK2(b0, bb.x, bb.y); PK2(b1, bb.z, bb.w);
#pragma unroll
            for (int i = 0; i < 4; i++) { o0[i] = b0; o1[i] = b1; }
        }
#pragma unroll
        for (int kk = 0; kk < 16; kk++) {
            F4U w0, w1, w2, w3;
            w0.f = *(float4*)&sm.sW2[(4 * kk + 0) * 32 + c2];
            w1.f = *(float4*)&sm.sW2[(4 * kk + 1) * 32 + c2];
            w2.f = *(float4*)&sm.sW2[(4 * kk + 2) * 32 + c2];
            w3.f = *(float4*)&sm.sW2[(4 * kk + 3) * 32 + c2];
#pragma unroll
            for (int i = 0; i < 4; i++) {
                int row = ty2 + 32 * i;
                float4 h4 = *(const float4*)&sm.sH[row * H_P + 4 * kk];
                ull p;
                PK2(p, h4.x, h4.x);
                FMA2(o0[i], p, w0.u[0], o0[i]); FMA2(o1[i], p, w0.u[1], o1[i]);
                PK2(p, h4.y, h4.y);
                FMA2(o0[i], p, w1.u[0], o0[i]); FMA2(o1[i], p, w1.u[1], o1[i]);
                PK2(p, h4.z, h4.z);
                FMA2(o0[i], p, w2.u[0], o0[i]); FMA2(o1[i], p, w2.u[1], o1[i]);
                PK2(p, h4.w, h4.w);
                FMA2(o0[i], p, w3.u[0], o0[i]); FMA2(o1[i], p, w3.u[1], o1[i]);
            }
        }
#pragma unroll
        for (int i = 0; i < 4; i++) {
            int row = ty2 + 32 * i;
            int e = eBase + row;
            if (e < E) {
                float4 o;
                UPK2(o.x, o.y, o0[i]);
                UPK2(o.z, o.w, o1[i]);
                *(float4*)(eout + (size_t)e * 32 + c2) = o;
                float* ap = g_agg + (size_t)sm.sDst[row] * 32 + c2;
                asm volatile("red.global.add.v4.f32 [%0], {%1,%2,%3,%4};"
                             :: "l"(ap), "f"(o.x), "f"(o.y), "f"(o.z), "f"(o.w)
                             : "memory");
            }
        }
    }
}

// ---------------- tiled node kernel: 128 nodes per 512-thread block (R8 proven variant) ----------------
#define TN 128

struct NSm {
    float sW1T[64 * 66];   // node W1 rows 0..63 transposed [c][k]
    float sW2T[32 * 66];
    float sU[MAXB * 64];
    float sb2[32];
    float sB[MAXB * 32];
    float sXA[TN * 68];    // [row][k]: k 0..31 = x, 32..63 = agg/deg
    float sH[TN * 68];
    int sBt[TN];
};

__global__ void __launch_bounds__(512, 1) nodet_k(
    const float* __restrict__ x_in, float* __restrict__ x_out,
    const int* __restrict__ batch,
    const float* __restrict__ W1n, const float* __restrict__ W2n,
    const float* __restrict__ b2n, int N) {
    extern __shared__ char smem_raw[];
    NSm& sm = *(NSm*)smem_raw;

    int tid = threadIdx.x;
    int n0 = blockIdx.x * TN;

    for (int i = tid; i < 4096; i += 512) {
        int k = i >> 6, c = i & 63;
        sm.sW1T[c * 66 + k] = W1n[i];
    }
    for (int i = tid; i < 2048; i += 512) {
        int k = i >> 5, c = i & 31;
        sm.sW2T[c * 66 + k] = W2n[i];
    }
    for (int i = tid; i < 1024; i += 512) sm.sU[i] = g_uWn[i];
    if (tid < 32) sm.sb2[tid] = b2n[tid];
    sm.sB[tid] = 0.f;  // 512 entries, one per thread

    // stage x | agg/deg, 4 threads per row
    {
        int r = tid >> 2, sub = tid & 3;
        int n = n0 + r;
        if (sub == 0) sm.sBt[r] = (n < N) ? batch[n] : 0;
        float4 v0 = make_float4(0.f, 0.f, 0.f, 0.f), v1 = v0, v2 = v0, v3 = v0;
        if (n < N) {
            if (sub < 2) {
                const float4* p = (const float4*)(x_in + (size_t)n * 32 + sub * 16);
                v0 = p[0]; v1 = p[1]; v2 = p[2]; v3 = p[3];
            } else {
                float inv = 1.f / fmaxf(g_deg[n], 1.f);
                const float4* p = (const float4*)(g_agg + (size_t)n * 32 + (sub - 2) * 16);
                v0 = p[0]; v1 = p[1]; v2 = p[2]; v3 = p[3];
                v0.x *= inv; v0.y *= inv; v0.z *= inv; v0.w *= inv;
                v1.x *= inv; v1.y *= inv; v1.z *= inv; v1.w *= inv;
                v2.x *= inv; v2.y *= inv; v2.z *= inv; v2.w *= inv;
                v3.x *= inv; v3.y *= inv; v3.z *= inv; v3.w *= inv;
            }
        }
        float* base = &sm.sXA[r * 68 + (sub & 1) * 16 + ((sub >> 1) ? 32 : 0)];
        *(float4*)(base + 0) = v0;
        *(float4*)(base + 4) = v1;
        *(float4*)(base + 8) = v2;
        *(float4*)(base + 12) = v3;
    }
    __syncthreads();

    // GEMM1: H[128x64], thread tile 8 rows x 2 cols, k = 64
    {
        int tx = tid & 31, ty = tid >> 5;
        int r0 = ty * 8;
        int cA = tx, cB = tx + 32;
        ull accA[8], accB[8];
#pragma unroll
        for (int i = 0; i < 8; i++) {
            int bs = sm.sBt[r0 + i];
            PK2(accA[i], sm.sU[bs * 64 + cA], 0.f);
            PK2(accB[i], sm.sU[bs * 64 + cB], 0.f);
        }
#pragma unroll
        for (int t = 0; t < 32; t++) {
            ull wA = *(const ull*)&sm.sW1T[cA * 66 + 2 * t];
            ull wB = *(const ull*)&sm.sW1T[cB * 66 + 2 * t];
#pragma unroll
            for (int i = 0; i < 8; i++) {
                ull ev = *(const ull*)&sm.sXA[(r0 + i) * 68 + 2 * t];
                FMA2(accA[i], ev, wA, accA[i]);
                FMA2(accB[i], ev, wB, accB[i]);
            }
        }
#pragma unroll
        for (int i = 0; i < 8; i++) {
            float lo, hi;
            UPK2(lo, hi, accA[i]);
            sm.sH[(r0 + i) * 68 + cA] = fmaxf(lo + hi, 0.f);
            UPK2(lo, hi, accB[i]);
            sm.sH[(r0 + i) * 68 + cB] = fmaxf(lo + hi, 0.f);
        }
    }
    __syncthreads();

    // GEMM2: O[128x32], thread tile 2 rows x 4 cols
    {
        int tx2 = tid & 7, ty2 = tid >> 3;
        int r0 = ty2 * 2, c0 = tx2 * 4;
        ull o[2][4];
#pragma unroll
        for (int q = 0; q < 4; q++) {
            float bb = sm.sb2[c0 + q];
            PK2(o[0][q], bb, 0.f);
            PK2(o[1][q], bb, 0.f);
        }
#pragma unroll
        for (int t = 0; t < 32; t++) {
            ull w0 = *(const ull*)&sm.sW2T[(c0 + 0) * 66 + 2 * t];
            ull w1 = *(const ull*)&sm.sW2T[(c0 + 1) * 66 + 2 * t];
            ull w2v = *(const ull*)&sm.sW2T[(c0 + 2) * 66 + 2 * t];
            ull w3 = *(const ull*)&sm.sW2T[(c0 + 3) * 66 + 2 * t];
#pragma unroll
            for (int i = 0; i < 2; i++) {
                ull hp = *(const ull*)&sm.sH[(r0 + i) * 68 + 2 * t];
                FMA2(o[i][0], hp, w0, o[i][0]);
                FMA2(o[i][1], hp, w1, o[i][1]);
                FMA2(o[i][2], hp, w2v, o[i][2]);
                FMA2(o[i][3], hp, w3, o[i][3]);
            }
        }
#pragma unroll
        for (int i = 0; i < 2; i++) {
            int n = n0 + r0 + i;
            if (n < N) {
                float4 ov;
                float lo, hi;
                UPK2(lo, hi, o[i][0]); ov.x = lo + hi;
                UPK2(lo, hi, o[i][1]); ov.y = lo + hi;
                UPK2(lo, hi, o[i][2]); ov.z = lo + hi;
                UPK2(lo, hi, o[i][3]); ov.w = lo + hi;
                *(float4*)(x_out + (size_t)n * 32 + c0) = ov;
                int b = sm.sBt[r0 + i];
                float* bp = &sm.sB[b * 32 + c0];
                atomicAdd(bp + 0, ov.x);
                atomicAdd(bp + 1, ov.y);
                atomicAdd(bp + 2, ov.z);
                atomicAdd(bp + 3, ov.w);
            }
        }
    }
    __syncthreads();
    atomicAdd(&g_bsum[tid], sm.sB[tid]);  // 512 entries
}

// global model: u = MLP([u, bsum/gcnt])
__global__ void glob_k(const float* __restrict__ W1g, const float* __restrict__ b1g,
                       const float* __restrict__ W2g, const float* __restrict__ b2g,
                       float* __restrict__ out_u, int writeOut) {
    int b = blockIdx.x;
    int j = threadIdx.x;  // 64 threads
    __shared__ float gi[64];
    __shared__ float h[64];
    if (j < 32) gi[j] = g_u[b * 32 + j];
    else        gi[j] = g_bsum[b * 32 + (j - 32)] / fmaxf(g_gcnt[b], 1.f);
    __syncthreads();
    float acc = b1g[j];
#pragma unroll
    for (int k = 0; k < 64; k++) acc += gi[k] * W1g[k * 64 + j];
    h[j] = fmaxf(acc, 0.f);
    __syncthreads();
    if (j < 32) {
        float a2 = b2g[j];
#pragma unroll
        for (int k = 0; k < 64; k++) a2 += h[k] * W2g[k * 32 + j];
        g_u[b * 32 + j] = a2;
        if (writeOut) out_u[b * 32 + j] = a2;
    }
}

// ---------------- host launcher ----------------
extern "C" void kernel_launch(void* const* d_in, const int* in_sizes, int n_in,
                              void* d_out, int out_size) {
    const float* node_feats = (const float*)d_in[0];
    const int*   edge_index = (const int*)d_in[1];
    const float* edge_feats = (const float*)d_in[2];
    const float* glob_feats = (const float*)d_in[3];
    const int*   batch      = (const int*)d_in[4];
    const float* node_gamma = (const float*)d_in[5];
    const float* node_beta  = (const float*)d_in[6];
    const float* edge_gamma = (const float*)d_in[7];
    const float* edge_beta  = (const float*)d_in[8];
    const float* glob_gamma = (const float*)d_in[9];
    const float* glob_beta  = (const float*)d_in[10];
    const float* edge_W1 = (const float*)d_in[11];
    const float* edge_b1 = (const float*)d_in[12];
    const float* edge_W2 = (const float*)d_in[13];
    const float* edge_b2 = (const float*)d_in[14];
    const float* node_W1 = (const float*)d_in[15];
    const float* node_b1 = (const float*)d_in[16];
    const float* node_W2 = (const float*)d_in[17];
    const float* node_b2 = (const float*)d_in[18];
    const float* glob_W1 = (const float*)d_in[19];
    const float* glob_b1 = (const float*)d_in[20];
    const float* glob_W2 = (const float*)d_in[21];
    const float* glob_b2 = (const float*)d_in[22];

    const int N = in_sizes[0] / 32;
    const int E = in_sizes[1] / 2;
    const int B = in_sizes[3] / 32;
    const int* srcA = edge_index;
    const int* dstA = edge_index + E;

    float* out   = (float*)d_out;
    float* out_x = out;
    float* out_e = out + (size_t)N * 32;
    float* out_u = out_e + (size_t)E * 32;

    float *xa, *xb, *degp, *gcntp, *bsump;
    cudaGetSymbolAddress((void**)&xa, g_xa);
    cudaGetSymbolAddress((void**)&xb, g_xb);
    cudaGetSymbolAddress((void**)&degp, g_deg);
    cudaGetSymbolAddress((void**)&gcntp, g_gcnt);
    cudaGetSymbolAddress((void**)&bsump, g_bsum);

    static bool attr_set = false;
    if (!attr_set) {
        cudaFuncSetAttribute(edge2_k, cudaFuncAttributeMaxDynamicSharedMemorySize,
                             (int)sizeof(ESm));
        cudaFuncSetAttribute(nodet_k, cudaFuncAttributeMaxDynamicSharedMemorySize,
                             (int)sizeof(NSm));
        attr_set = true;
    }

    int eblocks = (E + TE - 1) / TE;
    int nblocks = (N + TN - 1) / TN;

    // ---- layer 0, ordered so edge2_k is my launch #4 (profiler skips 3) ----
    bn_k<<<(N * 32 + 255) / 256, 256>>>(node_feats, node_gamma, node_beta, xa, N * 32); // 1
    bnglob_uw_k<<<B, 128>>>(glob_feats, glob_gamma, glob_beta,
                            edge_W1 + 96 * 64, edge_b1,
                            node_W1 + 64 * 64, node_b1);                                // 2
    sd_k<<<(N + 255) / 256, 256>>>(xa, edge_W1, N, 1);                                  // 3 (+agg zero)
    edge2_k<<<eblocks, 256, sizeof(ESm)>>>(                                             // 4 (profiled)
        srcA, dstA, batch,
        edge_W1 + 64 * 64, edge_W2, edge_b2,
        edge_feats, edge_gamma, edge_beta, out_e, E);

    // index-structure denominators + bsum
    zero_k<<<(N + 255) / 256, 256>>>(degp, N);
    zero_k<<<1, 256>>>(gcntp, B);
    deg_k<<<(E + 255) / 256, 256>>>(dstA, E);
    gcnt_k<<<(N + 255) / 256, 256>>>(batch, N);
    zero_k<<<1, 512>>>(bsump, B * 32);

    nodet_k<<<nblocks, 512, sizeof(NSm)>>>(xa, xb, batch, node_W1, node_W2, node_b2, N);
    glob_k<<<B, 64>>>(glob_W1, glob_b1, glob_W2, glob_b2, out_u, 0);

    float* xcur = xb;
    for (int l = 1; l < 3; l++) {
        float* xnext = (l == 2) ? out_x : ((xcur == xa) ? xb : xa);

        zero_k<<<1, 512>>>(bsump, B * 32);
        uw_k<<<B, 128>>>(edge_W1 + l * 8192 + 96 * 64, edge_b1 + l * 64,
                         node_W1 + l * 6144 + 64 * 64, node_b1 + l * 64);
        sd_k<<<(N + 255) / 256, 256>>>(xcur, edge_W1 + l * 8192, N, 1);
        edge2_k<<<eblocks, 256, sizeof(ESm)>>>(
            srcA, dstA, batch,
            edge_W1 + l * 8192 + 64 * 64,
            edge_W2 + l * 2048, edge_b2 + l * 32,
            out_e, nullptr, nullptr, out_e, E);
        nodet_k<<<nblocks, 512, sizeof(NSm)>>>(xcur, xnext, batch,
                                               node_W1 + l * 6144,
                                               node_W2 + l * 2048, node_b2 + l * 32, N);
        glob_k<<<B, 64>>>(glob_W1 + l * 4096, glob_b1 + l * 64,
                          glob_W2 + l * 2048, glob_b2 + l * 32, out_u, (l == 2) ? 1 : 0);
        xcur = xnext;
    }
}

// round 14
// speedup vs baseline: 1.0877x; 1.0877x over previous
#include <cuda_runtime.h>

#define MAXN 50000
#define MAXB 16

typedef unsigned long long ull;

// packed f32x2 helpers (Blackwell double-rate fp32 path — ptxas never auto-emits)
#define PK2(out, lo, hi) asm("mov.b64 %0, {%1, %2};" : "=l"(out) : "f"(lo), "f"(hi))
#define UPK2(lo, hi, in) asm("mov.b64 {%0, %1}, %2;" : "=f"(lo), "=f"(hi) : "l"(in))
#define FMA2(d, a, b, c) asm("fma.rn.f32x2 %0, %1, %2, %3;" : "=l"(d) : "l"(a), "l"(b), "l"(c))

union F4U { float4 f; ull u[2]; };

// ---------------- device-global scratch (no allocations allowed) ----------------
__device__ float g_xa[MAXN * 32];
__device__ float g_xb[MAXN * 32];
__device__ float g_s[MAXN * 64];    // x[n] @ W1_edge[0:32,:]   (src block)
__device__ float g_d[MAXN * 64];    // x[n] @ W1_edge[32:64,:]  (dst block)
__device__ float g_agg[MAXN * 32];  // scatter-sum of e -> dst
__device__ float g_u[MAXB * 32];
__device__ float g_bsum[MAXB * 32]; // scatter-sum of x -> batch
__device__ float g_deg[MAXN];
__device__ float g_gcnt[MAXB];
__device__ float g_uWe[MAXB * 64];  // u @ W1_edge[96:128,:] + b1_edge
__device__ float g_uWn[MAXB * 64];  // u @ W1_node[64:96,:]  + b1_node

// ---------------- small utility kernels ----------------
__global__ void zero_k(float* p, int n) {
    int i = blockIdx.x * blockDim.x + threadIdx.x;
    if (i < n) p[i] = 0.f;
}

__global__ void bn_k(const float* __restrict__ x, const float* __restrict__ gamma,
                     const float* __restrict__ beta, float* __restrict__ y, int total) {
    int i = blockIdx.x * blockDim.x + threadIdx.x;
    if (i < total) {
        int c = i & 31;
        y[i] = x[i] * (gamma[c] * rsqrtf(1.f + 1e-5f)) + beta[c];
    }
}

__global__ void deg_k(const int* __restrict__ dst, int E) {
    int e = blockIdx.x * blockDim.x + threadIdx.x;
    if (e < E) atomicAdd(&g_deg[dst[e]], 1.f);
}

__global__ void gcnt_k(const int* __restrict__ batch, int N) {
    __shared__ float sc[MAXB];
    int tid = threadIdx.x;
    if (tid < MAXB) sc[tid] = 0.f;
    __syncthreads();
    int i = blockIdx.x * blockDim.x + tid;
    if (i < N) atomicAdd(&sc[batch[i]], 1.f);
    __syncthreads();
    if (tid < MAXB) atomicAdd(&g_gcnt[tid], sc[tid]);
}

// per-batch u contributions to the edge/node layer-1 activations (+bias)
__global__ void uw_k(const float* __restrict__ eW1u, const float* __restrict__ eb1,
                     const float* __restrict__ nW1u, const float* __restrict__ nb1) {
    int b = blockIdx.x;
    int t = threadIdx.x;
    int j = t & 63;
    const float* uu = g_u + b * 32;
    if (t < 64) {
        float acc = eb1[j];
#pragma unroll
        for (int k = 0; k < 32; k++) acc += uu[k] * eW1u[k * 64 + j];
        g_uWe[b * 64 + j] = acc;
    } else {
        float acc = nb1[j];
#pragma unroll
        for (int k = 0; k < 32; k++) acc += uu[k] * nW1u[k * 64 + j];
        g_uWn[b * 64 + j] = acc;
    }
}

// fused: glob BN -> g_u, then uWe/uWn precompute (layer 0)
__global__ void bnglob_uw_k(const float* __restrict__ glob_feats,
                            const float* __restrict__ gg, const float* __restrict__ gb,
                            const float* __restrict__ eW1u, const float* __restrict__ eb1,
                            const float* __restrict__ nW1u, const float* __restrict__ nb1) {
    int b = blockIdx.x;
    int t = threadIdx.x;  // 128
    __shared__ float su[32];
    if (t < 32) {
        float v = glob_feats[b * 32 + t] * (gg[t] * rsqrtf(1.f + 1e-5f)) + gb[t];
        g_u[b * 32 + t] = v;
        su[t] = v;
    }
    __syncthreads();
    int j = t & 63;
    if (t < 64) {
        float acc = eb1[j];
#pragma unroll
        for (int k = 0; k < 32; k++) acc += su[k] * eW1u[k * 64 + j];
        g_uWe[b * 64 + j] = acc;
    } else {
        float acc = nb1[j];
#pragma unroll
        for (int k = 0; k < 32; k++) acc += su[k] * nW1u[k * 64 + j];
        g_uWn[b * 64 + j] = acc;
    }
}

// per-node precompute: s[n] = x[n] @ W1e[0:32,:], d[n] = x[n] @ W1e[32:64,:]
// also zeroes g_agg row n (fused)
__global__ void __launch_bounds__(256) sd_k(const float* __restrict__ x,
                                            const float* __restrict__ W1sd, int N,
                                            int zeroAgg) {
    __shared__ float sW[64 * 64];
    int tid = threadIdx.x;
    for (int i = tid; i < 4096; i += 256) sW[i] = W1sd[i];
    __syncthreads();
    int n = blockIdx.x * 256 + tid;
    if (n >= N) return;

    if (zeroAgg) {
        float4 z = make_float4(0.f, 0.f, 0.f, 0.f);
        float4* az = (float4*)(g_agg + (size_t)n * 32);
#pragma unroll
        for (int q = 0; q < 8; q++) az[q] = z;
    }

    float xv[32];
    const float4* xp = (const float4*)(x + (size_t)n * 32);
#pragma unroll
    for (int k = 0; k < 8; k++) {
        float4 v = xp[k];
        xv[4 * k] = v.x; xv[4 * k + 1] = v.y; xv[4 * k + 2] = v.z; xv[4 * k + 3] = v.w;
    }

    ull acc[32];
#pragma unroll
    for (int j = 0; j < 32; j++) acc[j] = 0ull;
#pragma unroll 4
    for (int k = 0; k < 32; k++) {
        ull xkp; PK2(xkp, xv[k], xv[k]);
#pragma unroll
        for (int j4 = 0; j4 < 16; j4++) {
            F4U w; w.f = *(const float4*)&sW[k * 64 + j4 * 4];
            FMA2(acc[2 * j4], xkp, w.u[0], acc[2 * j4]);
            FMA2(acc[2 * j4 + 1], xkp, w.u[1], acc[2 * j4 + 1]);
        }
    }
    float4* sp = (float4*)(g_s + (size_t)n * 64);
#pragma unroll
    for (int j4 = 0; j4 < 16; j4++) {
        F4U o; o.u[0] = acc[2 * j4]; o.u[1] = acc[2 * j4 + 1];
        sp[j4] = o.f;
    }

#pragma unroll
    for (int j = 0; j < 32; j++) acc[j] = 0ull;
#pragma unroll 4
    for (int k = 0; k < 32; k++) {
        ull xkp; PK2(xkp, xv[k], xv[k]);
#pragma unroll
        for (int j4 = 0; j4 < 16; j4++) {
            F4U w; w.f = *(const float4*)&sW[(32 + k) * 64 + j4 * 4];
            FMA2(acc[2 * j4], xkp, w.u[0], acc[2 * j4]);
            FMA2(acc[2 * j4 + 1], xkp, w.u[1], acc[2 * j4 + 1]);
        }
    }
    float4* dp = (float4*)(g_d + (size_t)n * 64);
#pragma unroll
    for (int j4 = 0; j4 < 16; j4++) {
        F4U o; o.u[0] = acc[2 * j4]; o.u[1] = acc[2 * j4 + 1];
        dp[j4] = o.f;
    }
}

// ---------------- tiled edge kernel: 128 edges per 256-thread block ----------------
// R12 proven body; occupancy experiment: __launch_bounds__(256,3) caps regs ~85
// so 3 blocks/SM fit (24 warps vs 16 -> +50% latency hiding for gathers/atomics).
#define TE 128
#define EIN_P 34
#define H_P 66

struct ESm {
    float sWe[32 * 64];    // W1 e-block (rows 64..96)
    float sW2[64 * 32];
    float sU[MAXB * 64];
    float sb2[32];
    float sEin[TE * EIN_P];  // edge feats, pitch 34
    float sH[TE * H_P];      // hidden, pitch 66
    int sSrc[TE];
    int sDst[TE];
    int sBs[TE];
};

__global__ void __launch_bounds__(256, 3) edge2_k(
    const int* __restrict__ src, const int* __restrict__ dstA,
    const int* __restrict__ batch,
    const float* __restrict__ W1e, const float* __restrict__ W2,
    const float* __restrict__ b2,
    const float* __restrict__ ein,          // raw edge feats (l0) or current e
    const float* __restrict__ bn_gamma,     // non-null => apply BN to ein
    const float* __restrict__ bn_beta,
    float* __restrict__ eout, int E) {
    extern __shared__ char smem_raw[];
    ESm& sm = *(ESm*)smem_raw;

    int tid = threadIdx.x;
    int eBase = blockIdx.x * TE;

    // ---- stage weights / tables ----
    for (int i = tid; i < 2048; i += 256) { sm.sWe[i] = W1e[i]; sm.sW2[i] = W2[i]; }
    for (int i = tid; i < MAXB * 64; i += 256) sm.sU[i] = g_uWe[i];
    if (tid < 32) sm.sb2[tid] = b2[tid];

    // ---- stage indices ----
    if (tid < TE) {
        int e = eBase + tid;
        int s = 0, d = 0, bs = 0;
        if (e < E) { s = src[e]; d = dstA[e]; bs = batch[s]; }
        sm.sSrc[tid] = s; sm.sDst[tid] = d; sm.sBs[tid] = bs;
    }

    // ---- stage edge features (optionally with BN), 2 threads per edge, float2 stores ----
    {
        int el = tid >> 1;
        int e = eBase + el;
        int off = (tid & 1) * 16;
        if (e < E) {
            const float4* p = (const float4*)(ein + (size_t)e * 32 + off);
#pragma unroll
            for (int q = 0; q < 4; q++) {
                float4 v = p[q];
                if (bn_gamma) {
                    int c = off + 4 * q;
                    float r = rsqrtf(1.f + 1e-5f);
                    v.x = v.x * (__ldg(bn_gamma + c)     * r) + __ldg(bn_beta + c);
                    v.y = v.y * (__ldg(bn_gamma + c + 1) * r) + __ldg(bn_beta + c + 1);
                    v.z = v.z * (__ldg(bn_gamma + c + 2) * r) + __ldg(bn_beta + c + 2);
                    v.w = v.w * (__ldg(bn_gamma + c + 3) * r) + __ldg(bn_beta + c + 3);
                }
                float* b0 = &sm.sEin[el * EIN_P + off + 4 * q];
                *(float2*)(b0 + 0) = make_float2(v.x, v.y);
                *(float2*)(b0 + 2) = make_float2(v.z, v.w);
            }
        }
    }
    __syncthreads();

    // ---- GEMM1: H[128x64] = relu(s[src]+d[dst]+uWe[bs] + Ein[128x32] @ We[32x64]) ----
    {
        int tx = tid & 15, ty = tid >> 4;
        int r0 = ty * 8, c0 = tx * 4;
        ull acc0[8], acc1[8];
#pragma unroll
        for (int i = 0; i < 8; i++) {
            int s = sm.sSrc[r0 + i], d = sm.sDst[r0 + i], bs = sm.sBs[r0 + i];
            float4 a = *(const float4*)(g_s + (size_t)s * 64 + c0);
            float4 b = *(const float4*)(g_d + (size_t)d * 64 + c0);
            const float* up = sm.sU + bs * 64 + c0;
            PK2(acc0[i], a.x + b.x + up[0], a.y + b.y + up[1]);
            PK2(acc1[i], a.z + b.z + up[2], a.w + b.w + up[3]);
        }
#pragma unroll
        for (int k = 0; k < 32; k++) {
            F4U w; w.f = *(float4*)&sm.sWe[k * 64 + c0];
#pragma unroll
            for (int i = 0; i < 8; i++) {
                float ev = sm.sEin[(r0 + i) * EIN_P + k];
                ull evp; PK2(evp, ev, ev);
                FMA2(acc0[i], evp, w.u[0], acc0[i]);
                FMA2(acc1[i], evp, w.u[1], acc1[i]);
            }
        }
#pragma unroll
        for (int i = 0; i < 8; i++) {
            float lo, hi;
            float* hb = &sm.sH[(r0 + i) * H_P + c0];
            UPK2(lo, hi, acc0[i]);
            *(float2*)(hb + 0) = make_float2(fmaxf(lo, 0.f), fmaxf(hi, 0.f));
            UPK2(lo, hi, acc1[i]);
            *(float2*)(hb + 2) = make_float2(fmaxf(lo, 0.f), fmaxf(hi, 0.f));
        }
    }
    __syncthreads();

    // ---- GEMM2: O[128x32] = H @ W2[64x32] + b2; write e; scatter-add to agg ----
    {
        int tx2 = tid & 7, ty2 = tid >> 3;
        int r0 = ty2 * 4, c0 = tx2 * 4;
        ull o0[4], o1[4];
        {
            float4 bb = *(float4*)&sm.sb2[c0];
            ull b0, b1; PK2(b0, bb.x, bb.y); PK2(b1, bb.z, bb.w);
#pragma unroll
            for (int i = 0; i < 4; i++) { o0[i] = b0; o1[i] = b1; }
        }
#pragma unroll
        for (int k = 0; k < 64; k++) {
            F4U w; w.f = *(float4*)&sm.sW2[k * 32 + c0];
#pragma unroll
            for (int i = 0; i < 4; i++) {
                float hv = sm.sH[(r0 + i) * H_P + k];
                ull hp; PK2(hp, hv, hv);
                FMA2(o0[i], hp, w.u[0], o0[i]);
                FMA2(o1[i], hp, w.u[1], o1[i]);
            }
        }
#pragma unroll
        for (int i = 0; i < 4; i++) {
            int e = eBase + r0 + i;
            if (e < E) {
                float4 o;
                UPK2(o.x, o.y, o0[i]);
                UPK2(o.z, o.w, o1[i]);
                *(float4*)(eout + (size_t)e * 32 + c0) = o;
                float* ap = g_agg + (size_t)sm.sDst[r0 + i] * 32 + c0;
                asm volatile("red.global.add.v4.f32 [%0], {%1,%2,%3,%4};"
                             :: "l"(ap), "f"(o.x), "f"(o.y), "f"(o.z), "f"(o.w)
                             : "memory");
            }
        }
    }
}

// ---------------- tiled node kernel: 128 nodes per 512-thread block (R8 proven variant) ----------------
#define TN 128

struct NSm {
    float sW1T[64 * 66];   // node W1 rows 0..63 transposed [c][k]
    float sW2T[32 * 66];
    float sU[MAXB * 64];
    float sb2[32];
    float sB[MAXB * 32];
    float sXA[TN * 68];    // [row][k]: k 0..31 = x, 32..63 = agg/deg
    float sH[TN * 68];
    int sBt[TN];
};

__global__ void __launch_bounds__(512, 1) nodet_k(
    const float* __restrict__ x_in, float* __restrict__ x_out,
    const int* __restrict__ batch,
    const float* __restrict__ W1n, const float* __restrict__ W2n,
    const float* __restrict__ b2n, int N) {
    extern __shared__ char smem_raw[];
    NSm& sm = *(NSm*)smem_raw;

    int tid = threadIdx.x;
    int n0 = blockIdx.x * TN;

    for (int i = tid; i < 4096; i += 512) {
        int k = i >> 6, c = i & 63;
        sm.sW1T[c * 66 + k] = W1n[i];
    }
    for (int i = tid; i < 2048; i += 512) {
        int k = i >> 5, c = i & 31;
        sm.sW2T[c * 66 + k] = W2n[i];
    }
    for (int i = tid; i < 1024; i += 512) sm.sU[i] = g_uWn[i];
    if (tid < 32) sm.sb2[tid] = b2n[tid];
    sm.sB[tid] = 0.f;  // 512 entries, one per thread

    // stage x | agg/deg, 4 threads per row
    {
        int r = tid >> 2, sub = tid & 3;
        int n = n0 + r;
        if (sub == 0) sm.sBt[r] = (n < N) ? batch[n] : 0;
        float4 v0 = make_float4(0.f, 0.f, 0.f, 0.f), v1 = v0, v2 = v0, v3 = v0;
        if (n < N) {
            if (sub < 2) {
                const float4* p = (const float4*)(x_in + (size_t)n * 32 + sub * 16);
                v0 = p[0]; v1 = p[1]; v2 = p[2]; v3 = p[3];
            } else {
                float inv = 1.f / fmaxf(g_deg[n], 1.f);
                const float4* p = (const float4*)(g_agg + (size_t)n * 32 + (sub - 2) * 16);
                v0 = p[0]; v1 = p[1]; v2 = p[2]; v3 = p[3];
                v0.x *= inv; v0.y *= inv; v0.z *= inv; v0.w *= inv;
                v1.x *= inv; v1.y *= inv; v1.z *= inv; v1.w *= inv;
                v2.x *= inv; v2.y *= inv; v2.z *= inv; v2.w *= inv;
                v3.x *= inv; v3.y *= inv; v3.z *= inv; v3.w *= inv;
            }
        }
        float* base = &sm.sXA[r * 68 + (sub & 1) * 16 + ((sub >> 1) ? 32 : 0)];
        *(float4*)(base + 0) = v0;
        *(float4*)(base + 4) = v1;
        *(float4*)(base + 8) = v2;
        *(float4*)(base + 12) = v3;
    }
    __syncthreads();

    // GEMM1: H[128x64], thread tile 8 rows x 2 cols, k = 64
    {
        int tx = tid & 31, ty = tid >> 5;
        int r0 = ty * 8;
        int cA = tx, cB = tx + 32;
        ull accA[8], accB[8];
#pragma unroll
        for (int i = 0; i < 8; i++) {
            int bs = sm.sBt[r0 + i];
            PK2(accA[i], sm.sU[bs * 64 + cA], 0.f);
            PK2(accB[i], sm.sU[bs * 64 + cB], 0.f);
        }
#pragma unroll
        for (int t = 0; t < 32; t++) {
            ull wA = *(const ull*)&sm.sW1T[cA * 66 + 2 * t];
            ull wB = *(const ull*)&sm.sW1T[cB * 66 + 2 * t];
#pragma unroll
            for (int i = 0; i < 8; i++) {
                ull ev = *(const ull*)&sm.sXA[(r0 + i) * 68 + 2 * t];
                FMA2(accA[i], ev, wA, accA[i]);
                FMA2(accB[i], ev, wB, accB[i]);
            }
        }
#pragma unroll
        for (int i = 0; i < 8; i++) {
            float lo, hi;
            UPK2(lo, hi, accA[i]);
            sm.sH[(r0 + i) * 68 + cA] = fmaxf(lo + hi, 0.f);
            UPK2(lo, hi, accB[i]);
            sm.sH[(r0 + i) * 68 + cB] = fmaxf(lo + hi, 0.f);
        }
    }
    __syncthreads();

    // GEMM2: O[128x32], thread tile 2 rows x 4 cols
    {
        int tx2 = tid & 7, ty2 = tid >> 3;
        int r0 = ty2 * 2, c0 = tx2 * 4;
        ull o[2][4];
#pragma unroll
        for (int q = 0; q < 4; q++) {
            float bb = sm.sb2[c0 + q];
            PK2(o[0][q], bb, 0.f);
            PK2(o[1][q], bb, 0.f);
        }
#pragma unroll
        for (int t = 0; t < 32; t++) {
            ull w0 = *(const ull*)&sm.sW2T[(c0 + 0) * 66 + 2 * t];
            ull w1 = *(const ull*)&sm.sW2T[(c0 + 1) * 66 + 2 * t];
            ull w2v = *(const ull*)&sm.sW2T[(c0 + 2) * 66 + 2 * t];
            ull w3 = *(const ull*)&sm.sW2T[(c0 + 3) * 66 + 2 * t];
#pragma unroll
            for (int i = 0; i < 2; i++) {
                ull hp = *(const ull*)&sm.sH[(r0 + i) * 68 + 2 * t];
                FMA2(o[i][0], hp, w0, o[i][0]);
                FMA2(o[i][1], hp, w1, o[i][1]);
                FMA2(o[i][2], hp, w2v, o[i][2]);
                FMA2(o[i][3], hp, w3, o[i][3]);
            }
        }
#pragma unroll
        for (int i = 0; i < 2; i++) {
            int n = n0 + r0 + i;
            if (n < N) {
                float4 ov;
                float lo, hi;
                UPK2(lo, hi, o[i][0]); ov.x = lo + hi;
                UPK2(lo, hi, o[i][1]); ov.y = lo + hi;
                UPK2(lo, hi, o[i][2]); ov.z = lo + hi;
                UPK2(lo, hi, o[i][3]); ov.w = lo + hi;
                *(float4*)(x_out + (size_t)n * 32 + c0) = ov;
                int b = sm.sBt[r0 + i];
                float* bp = &sm.sB[b * 32 + c0];
                atomicAdd(bp + 0, ov.x);
                atomicAdd(bp + 1, ov.y);
                atomicAdd(bp + 2, ov.z);
                atomicAdd(bp + 3, ov.w);
            }
        }
    }
    __syncthreads();
    atomicAdd(&g_bsum[tid], sm.sB[tid]);  // 512 entries
}

// global model: u = MLP([u, bsum/gcnt])
__global__ void glob_k(const float* __restrict__ W1g, const float* __restrict__ b1g,
                       const float* __restrict__ W2g, const float* __restrict__ b2g,
                       float* __restrict__ out_u, int writeOut) {
    int b = blockIdx.x;
    int j = threadIdx.x;  // 64 threads
    __shared__ float gi[64];
    __shared__ float h[64];
    if (j < 32) gi[j] = g_u[b * 32 + j];
    else        gi[j] = g_bsum[b * 32 + (j - 32)] / fmaxf(g_gcnt[b], 1.f);
    __syncthreads();
    float acc = b1g[j];
#pragma unroll
    for (int k = 0; k < 64; k++) acc += gi[k] * W1g[k * 64 + j];
    h[j] = fmaxf(acc, 0.f);
    __syncthreads();
    if (j < 32) {
        float a2 = b2g[j];
#pragma unroll
        for (int k = 0; k < 64; k++) a2 += h[k] * W2g[k * 32 + j];
        g_u[b * 32 + j] = a2;
        if (writeOut) out_u[b * 32 + j] = a2;
    }
}

// ---------------- host launcher ----------------
extern "C" void kernel_launch(void* const* d_in, const int* in_sizes, int n_in,
                              void* d_out, int out_size) {
    const float* node_feats = (const float*)d_in[0];
    const int*   edge_index = (const int*)d_in[1];
    const float* edge_feats = (const float*)d_in[2];
    const float* glob_feats = (const float*)d_in[3];
    const int*   batch      = (const int*)d_in[4];
    const float* node_gamma = (const float*)d_in[5];
    const float* node_beta  = (const float*)d_in[6];
    const float* edge_gamma = (const float*)d_in[7];
    const float* edge_beta  = (const float*)d_in[8];
    const float* glob_gamma = (const float*)d_in[9];
    const float* glob_beta  = (const float*)d_in[10];
    const float* edge_W1 = (const float*)d_in[11];
    const float* edge_b1 = (const float*)d_in[12];
    const float* edge_W2 = (const float*)d_in[13];
    const float* edge_b2 = (const float*)d_in[14];
    const float* node_W1 = (const float*)d_in[15];
    const float* node_b1 = (const float*)d_in[16];
    const float* node_W2 = (const float*)d_in[17];
    const float* node_b2 = (const float*)d_in[18];
    const float* glob_W1 = (const float*)d_in[19];
    const float* glob_b1 = (const float*)d_in[20];
    const float* glob_W2 = (const float*)d_in[21];
    const float* glob_b2 = (const float*)d_in[22];

    const int N = in_sizes[0] / 32;
    const int E = in_sizes[1] / 2;
    const int B = in_sizes[3] / 32;
    const int* srcA = edge_index;
    const int* dstA = edge_index + E;

    float* out   = (float*)d_out;
    float* out_x = out;
    float* out_e = out + (size_t)N * 32;
    float* out_u = out_e + (size_t)E * 32;

    float *xa, *xb, *degp, *gcntp, *bsump;
    cudaGetSymbolAddress((void**)&xa, g_xa);
    cudaGetSymbolAddress((void**)&xb, g_xb);
    cudaGetSymbolAddress((void**)&degp, g_deg);
    cudaGetSymbolAddress((void**)&gcntp, g_gcnt);
    cudaGetSymbolAddress((void**)&bsump, g_bsum);

    static bool attr_set = false;
    if (!attr_set) {
        cudaFuncSetAttribute(edge2_k, cudaFuncAttributeMaxDynamicSharedMemorySize,
                             (int)sizeof(ESm));
        cudaFuncSetAttribute(nodet_k, cudaFuncAttributeMaxDynamicSharedMemorySize,
                             (int)sizeof(NSm));
        attr_set = true;
    }

    int eblocks = (E + TE - 1) / TE;
    int nblocks = (N + TN - 1) / TN;

    // ---- layer 0, ordered so edge2_k is my launch #4 (profiler skips 3) ----
    bn_k<<<(N * 32 + 255) / 256, 256>>>(node_feats, node_gamma, node_beta, xa, N * 32); // 1
    bnglob_uw_k<<<B, 128>>>(glob_feats, glob_gamma, glob_beta,
                            edge_W1 + 96 * 64, edge_b1,
                            node_W1 + 64 * 64, node_b1);                                // 2
    sd_k<<<(N + 255) / 256, 256>>>(xa, edge_W1, N, 1);                                  // 3 (+agg zero)
    edge2_k<<<eblocks, 256, sizeof(ESm)>>>(                                             // 4 (profiled)
        srcA, dstA, batch,
        edge_W1 + 64 * 64, edge_W2, edge_b2,
        edge_feats, edge_gamma, edge_beta, out_e, E);

    // index-structure denominators + bsum
    zero_k<<<(N + 255) / 256, 256>>>(degp, N);
    zero_k<<<1, 256>>>(gcntp, B);
    deg_k<<<(E + 255) / 256, 256>>>(dstA, E);
    gcnt_k<<<(N + 255) / 256, 256>>>(batch, N);
    zero_k<<<1, 512>>>(bsump, B * 32);

    nodet_k<<<nblocks, 512, sizeof(NSm)>>>(xa, xb, batch, node_W1, node_W2, node_b2, N);
    glob_k<<<B, 64>>>(glob_W1, glob_b1, glob_W2, glob_b2, out_u, 0);

    float* xcur = xb;
    for (int l = 1; l < 3; l++) {
        float* xnext = (l == 2) ? out_x : ((xcur == xa) ? xb : xa);

        zero_k<<<1, 512>>>(bsump, B * 32);
        uw_k<<<B, 128>>>(edge_W1 + l * 8192 + 96 * 64, edge_b1 + l * 64,
                         node_W1 + l * 6144 + 64 * 64, node_b1 + l * 64);
        sd_k<<<(N + 255) / 256, 256>>>(xcur, edge_W1 + l * 8192, N, 1);
        edge2_k<<<eblocks, 256, sizeof(ESm)>>>(
            srcA, dstA, batch,
            edge_W1 + l * 8192 + 64 * 64,
            edge_W2 + l * 2048, edge_b2 + l * 32,
            out_e, nullptr, nullptr, out_e, E);
        nodet_k<<<nblocks, 512, sizeof(NSm)>>>(xcur, xnext, batch,
                                               node_W1 + l * 6144,
                                               node_W2 + l * 2048, node_b2 + l * 32, N);
        glob_k<<<B, 64>>>(glob_W1 + l * 4096, glob_b1 + l * 64,
                          glob_W2 + l * 2048, glob_b2 + l * 32, out_u, (l == 2) ? 1 : 0);
        xcur = xnext;
    }
}

// round 16
// speedup vs baseline: 1.1016x; 1.0127x over previous
#include <cuda_runtime.h>

#define MAXN 50000
#define MAXB 16

typedef unsigned long long ull;

// packed f32x2 helpers (Blackwell double-rate fp32 path — ptxas never auto-emits)
#define PK2(out, lo, hi) asm("mov.b64 %0, {%1, %2};" : "=l"(out) : "f"(lo), "f"(hi))
#define UPK2(lo, hi, in) asm("mov.b64 {%0, %1}, %2;" : "=f"(lo), "=f"(hi) : "l"(in))
#define FMA2(d, a, b, c) asm("fma.rn.f32x2 %0, %1, %2, %3;" : "=l"(d) : "l"(a), "l"(b), "l"(c))

union F4U { float4 f; ull u[2]; };

// ---------------- device-global scratch (no allocations allowed) ----------------
__device__ float g_xa[MAXN * 32];
__device__ float g_xb[MAXN * 32];
__device__ float g_s[MAXN * 64];    // x[n] @ W1_edge[0:32,:]   (src block)
__device__ float g_d[MAXN * 64];    // x[n] @ W1_edge[32:64,:]  (dst block)
__device__ float g_agg[MAXN * 32];  // scatter-sum of e -> dst
__device__ float g_u[MAXB * 32];
__device__ float g_bsum[MAXB * 32]; // scatter-sum of x -> batch
__device__ float g_deg[MAXN];
__device__ float g_gcnt[MAXB];
__device__ float g_uWe[MAXB * 64];  // u @ W1_edge[96:128,:] + b1_edge
__device__ float g_uWn[MAXB * 64];  // u @ W1_node[64:96,:]  + b1_node

// ---------------- small utility kernels ----------------
__global__ void zero_k(float* p, int n) {
    int i = blockIdx.x * blockDim.x + threadIdx.x;
    if (i < n) p[i] = 0.f;
}

__global__ void bn_k(const float* __restrict__ x, const float* __restrict__ gamma,
                     const float* __restrict__ beta, float* __restrict__ y, int total) {
    int i = blockIdx.x * blockDim.x + threadIdx.x;
    if (i < total) {
        int c = i & 31;
        y[i] = x[i] * (gamma[c] * rsqrtf(1.f + 1e-5f)) + beta[c];
    }
}

__global__ void deg_k(const int* __restrict__ dst, int E) {
    int e = blockIdx.x * blockDim.x + threadIdx.x;
    if (e < E) atomicAdd(&g_deg[dst[e]], 1.f);
}

__global__ void gcnt_k(const int* __restrict__ batch, int N) {
    __shared__ float sc[MAXB];
    int tid = threadIdx.x;
    if (tid < MAXB) sc[tid] = 0.f;
    __syncthreads();
    int i = blockIdx.x * blockDim.x + tid;
    if (i < N) atomicAdd(&sc[batch[i]], 1.f);
    __syncthreads();
    if (tid < MAXB) atomicAdd(&g_gcnt[tid], sc[tid]);
}

// per-batch u contributions to the edge/node layer-1 activations (+bias)
__global__ void uw_k(const float* __restrict__ eW1u, const float* __restrict__ eb1,
                     const float* __restrict__ nW1u, const float* __restrict__ nb1) {
    int b = blockIdx.x;
    int t = threadIdx.x;
    int j = t & 63;
    const float* uu = g_u + b * 32;
    if (t < 64) {
        float acc = eb1[j];
#pragma unroll
        for (int k = 0; k < 32; k++) acc += uu[k] * eW1u[k * 64 + j];
        g_uWe[b * 64 + j] = acc;
    } else {
        float acc = nb1[j];
#pragma unroll
        for (int k = 0; k < 32; k++) acc += uu[k] * nW1u[k * 64 + j];
        g_uWn[b * 64 + j] = acc;
    }
}

// fused: glob BN -> g_u, then uWe/uWn precompute (layer 0)
__global__ void bnglob_uw_k(const float* __restrict__ glob_feats,
                            const float* __restrict__ gg, const float* __restrict__ gb,
                            const float* __restrict__ eW1u, const float* __restrict__ eb1,
                            const float* __restrict__ nW1u, const float* __restrict__ nb1) {
    int b = blockIdx.x;
    int t = threadIdx.x;  // 128
    __shared__ float su[32];
    if (t < 32) {
        float v = glob_feats[b * 32 + t] * (gg[t] * rsqrtf(1.f + 1e-5f)) + gb[t];
        g_u[b * 32 + t] = v;
        su[t] = v;
    }
    __syncthreads();
    int j = t & 63;
    if (t < 64) {
        float acc = eb1[j];
#pragma unroll
        for (int k = 0; k < 32; k++) acc += su[k] * eW1u[k * 64 + j];
        g_uWe[b * 64 + j] = acc;
    } else {
        float acc = nb1[j];
#pragma unroll
        for (int k = 0; k < 32; k++) acc += su[k] * nW1u[k * 64 + j];
        g_uWn[b * 64 + j] = acc;
    }
}

// per-node precompute: s[n] = x[n] @ W1e[0:32,:], d[n] = x[n] @ W1e[32:64,:]
// also zeroes g_agg row n (fused)
__global__ void __launch_bounds__(256) sd_k(const float* __restrict__ x,
                                            const float* __restrict__ W1sd, int N,
                                            int zeroAgg) {
    __shared__ float sW[64 * 64];
    int tid = threadIdx.x;
    for (int i = tid; i < 4096; i += 256) sW[i] = W1sd[i];
    __syncthreads();
    int n = blockIdx.x * 256 + tid;
    if (n >= N) return;

    if (zeroAgg) {
        float4 z = make_float4(0.f, 0.f, 0.f, 0.f);
        float4* az = (float4*)(g_agg + (size_t)n * 32);
#pragma unroll
        for (int q = 0; q < 8; q++) az[q] = z;
    }

    float xv[32];
    const float4* xp = (const float4*)(x + (size_t)n * 32);
#pragma unroll
    for (int k = 0; k < 8; k++) {
        float4 v = xp[k];
        xv[4 * k] = v.x; xv[4 * k + 1] = v.y; xv[4 * k + 2] = v.z; xv[4 * k + 3] = v.w;
    }

    ull acc[32];
#pragma unroll
    for (int j = 0; j < 32; j++) acc[j] = 0ull;
#pragma unroll 4
    for (int k = 0; k < 32; k++) {
        ull xkp; PK2(xkp, xv[k], xv[k]);
#pragma unroll
        for (int j4 = 0; j4 < 16; j4++) {
            F4U w; w.f = *(const float4*)&sW[k * 64 + j4 * 4];
            FMA2(acc[2 * j4], xkp, w.u[0], acc[2 * j4]);
            FMA2(acc[2 * j4 + 1], xkp, w.u[1], acc[2 * j4 + 1]);
        }
    }
    float4* sp = (float4*)(g_s + (size_t)n * 64);
#pragma unroll
    for (int j4 = 0; j4 < 16; j4++) {
        F4U o; o.u[0] = acc[2 * j4]; o.u[1] = acc[2 * j4 + 1];
        sp[j4] = o.f;
    }

#pragma unroll
    for (int j = 0; j < 32; j++) acc[j] = 0ull;
#pragma unroll 4
    for (int k = 0; k < 32; k++) {
        ull xkp; PK2(xkp, xv[k], xv[k]);
#pragma unroll
        for (int j4 = 0; j4 < 16; j4++) {
            F4U w; w.f = *(const float4*)&sW[(32 + k) * 64 + j4 * 4];
            FMA2(acc[2 * j4], xkp, w.u[0], acc[2 * j4]);
            FMA2(acc[2 * j4 + 1], xkp, w.u[1], acc[2 * j4 + 1]);
        }
    }
    float4* dp = (float4*)(g_d + (size_t)n * 64);
#pragma unroll
    for (int j4 = 0; j4 < 16; j4++) {
        F4U o; o.u[0] = acc[2 * j4]; o.u[1] = acc[2 * j4 + 1];
        dp[j4] = o.f;
    }
}

// ---------------- tiled edge kernel: 128 edges per 256-thread block ----------------
// Narrow-column tiles to halve smem weight traffic (the measured L1TEX wall):
//   GEMM1: 16 rows x 2 cols per thread (weights LDS.64, 256B/k vs 512B/k)
//   GEMM2:  8 rows x 2 cols per thread (weights LDS.64, 128B/k vs 512B/k)
// Activations loaded as float4 per 4 k-steps (broadcast).
#define TE 128
#define EIN_P 36
#define H_P 68

struct ESm {
    float sWe[32 * 64];      // W1 e-block (rows 64..96), [k][c]
    float sW2[64 * 32];      // [k][c]
    float sU[MAXB * 64];
    float sb2[32];
    float sEin[TE * EIN_P];  // edge feats [row][k], pitch 36 (float4-aligned)
    float sH[TE * H_P];      // hidden [row][k], pitch 68 (float4-aligned)
    int sSrc[TE];
    int sDst[TE];
    int sBs[TE];
};

__global__ void __launch_bounds__(256, 3) edge2_k(
    const int* __restrict__ src, const int* __restrict__ dstA,
    const int* __restrict__ batch,
    const float* __restrict__ W1e, const float* __restrict__ W2,
    const float* __restrict__ b2,
    const float* __restrict__ ein,          // raw edge feats (l0) or current e
    const float* __restrict__ bn_gamma,     // non-null => apply BN to ein
    const float* __restrict__ bn_beta,
    float* __restrict__ eout, int E) {
    extern __shared__ char smem_raw[];
    ESm& sm = *(ESm*)smem_raw;

    int tid = threadIdx.x;
    int eBase = blockIdx.x * TE;

    // ---- stage weights / tables ----
    for (int i = tid; i < 2048; i += 256) { sm.sWe[i] = W1e[i]; sm.sW2[i] = W2[i]; }
    for (int i = tid; i < MAXB * 64; i += 256) sm.sU[i] = g_uWe[i];
    if (tid < 32) sm.sb2[tid] = b2[tid];

    // ---- stage indices ----
    if (tid < TE) {
        int e = eBase + tid;
        int s = 0, d = 0, bs = 0;
        if (e < E) { s = src[e]; d = dstA[e]; bs = batch[s]; }
        sm.sSrc[tid] = s; sm.sDst[tid] = d; sm.sBs[tid] = bs;
    }

    // ---- stage edge features (optionally with BN), 2 threads per edge, float4 stores ----
    {
        int el = tid >> 1;
        int e = eBase + el;
        int off = (tid & 1) * 16;
        if (e < E) {
            const float4* p = (const float4*)(ein + (size_t)e * 32 + off);
#pragma unroll
            for (int q = 0; q < 4; q++) {
                float4 v = p[q];
                if (bn_gamma) {
                    int c = off + 4 * q;
                    float r = rsqrtf(1.f + 1e-5f);
                    v.x = v.x * (__ldg(bn_gamma + c)     * r) + __ldg(bn_beta + c);
                    v.y = v.y * (__ldg(bn_gamma + c + 1) * r) + __ldg(bn_beta + c + 1);
                    v.z = v.z * (__ldg(bn_gamma + c + 2) * r) + __ldg(bn_beta + c + 2);
                    v.w = v.w * (__ldg(bn_gamma + c + 3) * r) + __ldg(bn_beta + c + 3);
                }
                *(float4*)&sm.sEin[el * EIN_P + off + 4 * q] = v;
            }
        }
    }
    __syncthreads();

    // ---- GEMM1: H[128x64] = relu(s[src]+d[dst]+uWe[bs] + Ein[128x32] @ We[32x64]) ----
    // 256 threads, tile = 16 rows x 2 cols; weight = 1 LDS.64 per k (256B/warp/k).
    {
        int tx = tid & 31, ty = tid >> 5;
        int c0 = 2 * tx;
        int r0 = ty * 16;
        ull acc[16];
#pragma unroll
        for (int i = 0; i < 16; i++) {
            int row = r0 + i;
            int s = sm.sSrc[row], d = sm.sDst[row], bs = sm.sBs[row];
            float2 a = *(const float2*)(g_s + (size_t)s * 64 + c0);
            float2 b = *(const float2*)(g_d + (size_t)d * 64 + c0);
            const float* up = sm.sU + bs * 64 + c0;
            PK2(acc[i], a.x + b.x + up[0], a.y + b.y + up[1]);
        }
#pragma unroll
        for (int kk = 0; kk < 8; kk++) {
            ull w0 = *(const ull*)&sm.sWe[(4 * kk + 0) * 64 + c0];
            ull w1 = *(const ull*)&sm.sWe[(4 * kk + 1) * 64 + c0];
            ull w2 = *(const ull*)&sm.sWe[(4 * kk + 2) * 64 + c0];
            ull w3 = *(const ull*)&sm.sWe[(4 * kk + 3) * 64 + c0];
#pragma unroll
            for (int i = 0; i < 16; i++) {
                float4 e4 = *(const float4*)&sm.sEin[(r0 + i) * EIN_P + 4 * kk];
                ull p;
                PK2(p, e4.x, e4.x); FMA2(acc[i], p, w0, acc[i]);
                PK2(p, e4.y, e4.y); FMA2(acc[i], p, w1, acc[i]);
                PK2(p, e4.z, e4.z); FMA2(acc[i], p, w2, acc[i]);
                PK2(p, e4.w, e4.w); FMA2(acc[i], p, w3, acc[i]);
            }
        }
#pragma unroll
        for (int i = 0; i < 16; i++) {
            float lo, hi;
            UPK2(lo, hi, acc[i]);
            *(float2*)&sm.sH[(r0 + i) * H_P + c0] =
                make_float2(fmaxf(lo, 0.f), fmaxf(hi, 0.f));
        }
    }
    __syncthreads();

    // ---- GEMM2: O[128x32] = H @ W2[64x32] + b2; write e; scatter-add to agg ----
    // 256 threads, tile = 8 rows x 2 cols; weight = 1 LDS.64 per k (128B/warp/k).
    {
        int tx2 = tid & 15, ty2 = tid >> 4;
        int c2 = 2 * tx2;
        int r0 = ty2 * 8;
        ull o[8];
        {
            float2 bb = *(const float2*)&sm.sb2[c2];
            ull b0; PK2(b0, bb.x, bb.y);
#pragma unroll
            for (int i = 0; i < 8; i++) o[i] = b0;
        }
#pragma unroll
        for (int kk = 0; kk < 16; kk++) {
            ull w0 = *(const ull*)&sm.sW2[(4 * kk + 0) * 32 + c2];
            ull w1 = *(const ull*)&sm.sW2[(4 * kk + 1) * 32 + c2];
            ull w2 = *(const ull*)&sm.sW2[(4 * kk + 2) * 32 + c2];
            ull w3 = *(const ull*)&sm.sW2[(4 * kk + 3) * 32 + c2];
#pragma unroll
            for (int i = 0; i < 8; i++) {
                float4 h4 = *(const float4*)&sm.sH[(r0 + i) * H_P + 4 * kk];
                ull p;
                PK2(p, h4.x, h4.x); FMA2(o[i], p, w0, o[i]);
                PK2(p, h4.y, h4.y); FMA2(o[i], p, w1, o[i]);
                PK2(p, h4.z, h4.z); FMA2(o[i], p, w2, o[i]);
                PK2(p, h4.w, h4.w); FMA2(o[i], p, w3, o[i]);
            }
        }
#pragma unroll
        for (int i = 0; i < 8; i++) {
            int row = r0 + i;
            int e = eBase + row;
            if (e < E) {
                float lo, hi;
                UPK2(lo, hi, o[i]);
                *(float2*)(eout + (size_t)e * 32 + c2) = make_float2(lo, hi);
                float* ap = g_agg + (size_t)sm.sDst[row] * 32 + c2;
                asm volatile("red.global.add.v2.f32 [%0], {%1,%2};"
                             :: "l"(ap), "f"(lo), "f"(hi)
                             : "memory");
            }
        }
    }
}

// ---------------- tiled node kernel: 128 nodes per 512-thread block (R8 proven variant) ----------------
#define TN 128

struct NSm {
    float sW1T[64 * 66];   // node W1 rows 0..63 transposed [c][k]
    float sW2T[32 * 66];
    float sU[MAXB * 64];
    float sb2[32];
    float sB[MAXB * 32];
    float sXA[TN * 68];    // [row][k]: k 0..31 = x, 32..63 = agg/deg
    float sH[TN * 68];
    int sBt[TN];
};

__global__ void __launch_bounds__(512, 1) nodet_k(
    const float* __restrict__ x_in, float* __restrict__ x_out,
    const int* __restrict__ batch,
    const float* __restrict__ W1n, const float* __restrict__ W2n,
    const float* __restrict__ b2n, int N) {
    extern __shared__ char smem_raw[];
    NSm& sm = *(NSm*)smem_raw;

    int tid = threadIdx.x;
    int n0 = blockIdx.x * TN;

    for (int i = tid; i < 4096; i += 512) {
        int k = i >> 6, c = i & 63;
        sm.sW1T[c * 66 + k] = W1n[i];
    }
    for (int i = tid; i < 2048; i += 512) {
        int k = i >> 5, c = i & 31;
        sm.sW2T[c * 66 + k] = W2n[i];
    }
    for (int i = tid; i < 1024; i += 512) sm.sU[i] = g_uWn[i];
    if (tid < 32) sm.sb2[tid] = b2n[tid];
    sm.sB[tid] = 0.f;  // 512 entries, one per thread

    // stage x | agg/deg, 4 threads per row
    {
        int r = tid >> 2, sub = tid & 3;
        int n = n0 + r;
        if (sub == 0) sm.sBt[r] = (n < N) ? batch[n] : 0;
        float4 v0 = make_float4(0.f, 0.f, 0.f, 0.f), v1 = v0, v2 = v0, v3 = v0;
        if (n < N) {
            if (sub < 2) {
                const float4* p = (const float4*)(x_in + (size_t)n * 32 + sub * 16);
                v0 = p[0]; v1 = p[1]; v2 = p[2]; v3 = p[3];
            } else {
                float inv = 1.f / fmaxf(g_deg[n], 1.f);
                const float4* p = (const float4*)(g_agg + (size_t)n * 32 + (sub - 2) * 16);
                v0 = p[0]; v1 = p[1]; v2 = p[2]; v3 = p[3];
                v0.x *= inv; v0.y *= inv; v0.z *= inv; v0.w *= inv;
                v1.x *= inv; v1.y *= inv; v1.z *= inv; v1.w *= inv;
                v2.x *= inv; v2.y *= inv; v2.z *= inv; v2.w *= inv;
                v3.x *= inv; v3.y *= inv; v3.z *= inv; v3.w *= inv;
            }
        }
        float* base = &sm.sXA[r * 68 + (sub & 1) * 16 + ((sub >> 1) ? 32 : 0)];
        *(float4*)(base + 0) = v0;
        *(float4*)(base + 4) = v1;
        *(float4*)(base + 8) = v2;
        *(float4*)(base + 12) = v3;
    }
    __syncthreads();

    // GEMM1: H[128x64], thread tile 8 rows x 2 cols, k = 64
    {
        int tx = tid & 31, ty = tid >> 5;
        int r0 = ty * 8;
        int cA = tx, cB = tx + 32;
        ull accA[8], accB[8];
#pragma unroll
        for (int i = 0; i < 8; i++) {
            int bs = sm.sBt[r0 + i];
            PK2(accA[i], sm.sU[bs * 64 + cA], 0.f);
            PK2(accB[i], sm.sU[bs * 64 + cB], 0.f);
        }
#pragma unroll
        for (int t = 0; t < 32; t++) {
            ull wA = *(const ull*)&sm.sW1T[cA * 66 + 2 * t];
            ull wB = *(const ull*)&sm.sW1T[cB * 66 + 2 * t];
#pragma unroll
            for (int i = 0; i < 8; i++) {
                ull ev = *(const ull*)&sm.sXA[(r0 + i) * 68 + 2 * t];
                FMA2(accA[i], ev, wA, accA[i]);
                FMA2(accB[i], ev, wB, accB[i]);
            }
        }
#pragma unroll
        for (int i = 0; i < 8; i++) {
            float lo, hi;
            UPK2(lo, hi, accA[i]);
            sm.sH[(r0 + i) * 68 + cA] = fmaxf(lo + hi, 0.f);
            UPK2(lo, hi, accB[i]);
            sm.sH[(r0 + i) * 68 + cB] = fmaxf(lo + hi, 0.f);
        }
    }
    __syncthreads();

    // GEMM2: O[128x32], thread tile 2 rows x 4 cols
    {
        int tx2 = tid & 7, ty2 = tid >> 3;
        int r0 = ty2 * 2, c0 = tx2 * 4;
        ull o[2][4];
#pragma unroll
        for (int q = 0; q < 4; q++) {
            float bb = sm.sb2[c0 + q];
            PK2(o[0][q], bb, 0.f);
            PK2(o[1][q], bb, 0.f);
        }
#pragma unroll
        for (int t = 0; t < 32; t++) {
            ull w0 = *(const ull*)&sm.sW2T[(c0 + 0) * 66 + 2 * t];
            ull w1 = *(const ull*)&sm.sW2T[(c0 + 1) * 66 + 2 * t];
            ull w2v = *(const ull*)&sm.sW2T[(c0 + 2) * 66 + 2 * t];
            ull w3 = *(const ull*)&sm.sW2T[(c0 + 3) * 66 + 2 * t];
#pragma unroll
            for (int i = 0; i < 2; i++) {
                ull hp = *(const ull*)&sm.sH[(r0 + i) * 68 + 2 * t];
                FMA2(o[i][0], hp, w0, o[i][0]);
                FMA2(o[i][1], hp, w1, o[i][1]);
                FMA2(o[i][2], hp, w2v, o[i][2]);
                FMA2(o[i][3], hp, w3, o[i][3]);
            }
        }
#pragma unroll
        for (int i = 0; i < 2; i++) {
            int n = n0 + r0 + i;
            if (n < N) {
                float4 ov;
                float lo, hi;
                UPK2(lo, hi, o[i][0]); ov.x = lo + hi;
                UPK2(lo, hi, o[i][1]); ov.y = lo + hi;
                UPK2(lo, hi, o[i][2]); ov.z = lo + hi;
                UPK2(lo, hi, o[i][3]); ov.w = lo + hi;
                *(float4*)(x_out + (size_t)n * 32 + c0) = ov;
                int b = sm.sBt[r0 + i];
                float* bp = &sm.sB[b * 32 + c0];
                atomicAdd(bp + 0, ov.x);
                atomicAdd(bp + 1, ov.y);
                atomicAdd(bp + 2, ov.z);
                atomicAdd(bp + 3, ov.w);
            }
        }
    }
    __syncthreads();
    atomicAdd(&g_bsum[tid], sm.sB[tid]);  // 512 entries
}

// global model: u = MLP([u, bsum/gcnt])
__global__ void glob_k(const float* __restrict__ W1g, const float* __restrict__ b1g,
                       const float* __restrict__ W2g, const float* __restrict__ b2g,
                       float* __restrict__ out_u, int writeOut) {
    int b = blockIdx.x;
    int j = threadIdx.x;  // 64 threads
    __shared__ float gi[64];
    __shared__ float h[64];
    if (j < 32) gi[j] = g_u[b * 32 + j];
    else        gi[j] = g_bsum[b * 32 + (j - 32)] / fmaxf(g_gcnt[b], 1.f);
    __syncthreads();
    float acc = b1g[j];
#pragma unroll
    for (int k = 0; k < 64; k++) acc += gi[k] * W1g[k * 64 + j];
    h[j] = fmaxf(acc, 0.f);
    __syncthreads();
    if (j < 32) {
        float a2 = b2g[j];
#pragma unroll
        for (int k = 0; k < 64; k++) a2 += h[k] * W2g[k * 32 + j];
        g_u[b * 32 + j] = a2;
        if (writeOut) out_u[b * 32 + j] = a2;
    }
}

// ---------------- host launcher ----------------
extern "C" void kernel_launch(void* const* d_in, const int* in_sizes, int n_in,
                              void* d_out, int out_size) {
    const float* node_feats = (const float*)d_in[0];
    const int*   edge_index = (const int*)d_in[1];
    const float* edge_feats = (const float*)d_in[2];
    const float* glob_feats = (const float*)d_in[3];
    const int*   batch      = (const int*)d_in[4];
    const float* node_gamma = (const float*)d_in[5];
    const float* node_beta  = (const float*)d_in[6];
    const float* edge_gamma = (const float*)d_in[7];
    const float* edge_beta  = (const float*)d_in[8];
    const float* glob_gamma = (const float*)d_in[9];
    const float* glob_beta  = (const float*)d_in[10];
    const float* edge_W1 = (const float*)d_in[11];
    const float* edge_b1 = (const float*)d_in[12];
    const float* edge_W2 = (const float*)d_in[13];
    const float* edge_b2 = (const float*)d_in[14];
    const float* node_W1 = (const float*)d_in[15];
    const float* node_b1 = (const float*)d_in[16];
    const float* node_W2 = (const float*)d_in[17];
    const float* node_b2 = (const float*)d_in[18];
    const float* glob_W1 = (const float*)d_in[19];
    const float* glob_b1 = (const float*)d_in[20];
    const float* glob_W2 = (const float*)d_in[21];
    const float* glob_b2 = (const float*)d_in[22];

    const int N = in_sizes[0] / 32;
    const int E = in_sizes[1] / 2;
    const int B = in_sizes[3] / 32;
    const int* srcA = edge_index;
    const int* dstA = edge_index + E;

    float* out   = (float*)d_out;
    float* out_x = out;
    float* out_e = out + (size_t)N * 32;
    float* out_u = out_e + (size_t)E * 32;

    float *xa, *xb, *degp, *gcntp, *bsump;
    cudaGetSymbolAddress((void**)&xa, g_xa);
    cudaGetSymbolAddress((void**)&xb, g_xb);
    cudaGetSymbolAddress((void**)&degp, g_deg);
    cudaGetSymbolAddress((void**)&gcntp, g_gcnt);
    cudaGetSymbolAddress((void**)&bsump, g_bsum);

    static bool attr_set = false;
    if (!attr_set) {
        cudaFuncSetAttribute(edge2_k, cudaFuncAttributeMaxDynamicSharedMemorySize,
                             (int)sizeof(ESm));
        cudaFuncSetAttribute(nodet_k, cudaFuncAttributeMaxDynamicSharedMemorySize,
                             (int)sizeof(NSm));
        attr_set = true;
    }

    int eblocks = (E + TE - 1) / TE;
    int nblocks = (N + TN - 1) / TN;

    // ---- layer 0, ordered so edge2_k is my launch #4 (profiler skips 3) ----
    bn_k<<<(N * 32 + 255) / 256, 256>>>(node_feats, node_gamma, node_beta, xa, N * 32); // 1
    bnglob_uw_k<<<B, 128>>>(glob_feats, glob_gamma, glob_beta,
                            edge_W1 + 96 * 64, edge_b1,
                            node_W1 + 64 * 64, node_b1);                                // 2
    sd_k<<<(N + 255) / 256, 256>>>(xa, edge_W1, N, 1);                                  // 3 (+agg zero)
    edge2_k<<<eblocks, 256, sizeof(ESm)>>>(                                             // 4 (profiled)
        srcA, dstA, batch,
        edge_W1 + 64 * 64, edge_W2, edge_b2,
        edge_feats, edge_gamma, edge_beta, out_e, E);

    // index-structure denominators + bsum
    zero_k<<<(N + 255) / 256, 256>>>(degp, N);
    zero_k<<<1, 256>>>(gcntp, B);
    deg_k<<<(E + 255) / 256, 256>>>(dstA, E);
    gcnt_k<<<(N + 255) / 256, 256>>>(batch, N);
    zero_k<<<1, 512>>>(bsump, B * 32);

    nodet_k<<<nblocks, 512, sizeof(NSm)>>>(xa, xb, batch, node_W1, node_W2, node_b2, N);
    glob_k<<<B, 64>>>(glob_W1, glob_b1, glob_W2, glob_b2, out_u, 0);

    float* xcur = xb;
    for (int l = 1; l < 3; l++) {
        float* xnext = (l == 2) ? out_x : ((xcur == xa) ? xb : xa);

        zero_k<<<1, 512>>>(bsump, B * 32);
        uw_k<<<B, 128>>>(edge_W1 + l * 8192 + 96 * 64, edge_b1 + l * 64,
                         node_W1 + l * 6144 + 64 * 64, node_b1 + l * 64);
        sd_k<<<(N + 255) / 256, 256>>>(xcur, edge_W1 + l * 8192, N, 1);
        edge2_k<<<eblocks, 256, sizeof(ESm)>>>(
            srcA, dstA, batch,
            edge_W1 + l * 8192 + 64 * 64,
            edge_W2 + l * 2048, edge_b2 + l * 32,
            out_e, nullptr, nullptr, out_e, E);
        nodet_k<<<nblocks, 512, sizeof(NSm)>>>(xcur, xnext, batch,
                                               node_W1 + l * 6144,
                                               node_W2 + l * 2048, node_b2 + l * 32, N);
        glob_k<<<B, 64>>>(glob_W1 + l * 4096, glob_b1 + l * 64,
                          glob_W2 + l * 2048, glob_b2 + l * 32, out_u, (l == 2) ? 1 : 0);
        xcur = xnext;
    }
}